// round 9
// baseline (speedup 1.0000x reference)
#include <cuda_runtime.h>
#include <cuda_bf16.h>
#include <cstdint>
#include <math.h>

// ---------------- problem constants ----------------
#define DF      128
#define HID     128
#define KDIM    256
#define TILE_M  128
#define THREADS 512
#define GRID    148

// smem element strides: ldmatrix row addresses hit 8 distinct 16B slots mod 128B
// (144 % 128 = 16, 528 % 128 = 16)
#define AKS     72           // A row stride (elements); rows = edges, cols = 64-k chunk
#define BKS     264          // B row stride (elements); rows = n, cols = k(256)

#define A_TERM_BYTES  18432              // 128 * 72 * 2
#define A_BUF_BYTES   36864              // hi + lo

// ---------------- smem layout (byte offsets) ----------------
#define OFF_BHI   0                      // 128 x 264 bf16 = 67584
#define OFF_BLO   67584
#define OFF_A     135168                 // [buf2][term2] x 18432 = 73728
#define OFF_B1    208896
#define OFF_W3    209408
#define OFF_PART  209920                 // 128 x 4 x f32
#define SMEM_REQ  211968

__device__ __forceinline__ uint32_t smem_u32(const void* p) {
    uint32_t a;
    asm("{ .reg .u64 t; cvta.to.shared.u64 t, %1; cvt.u32.u64 %0, t; }"
        : "=r"(a) : "l"(p));
    return a;
}

// pack (f0 -> low half, f1 -> high half)
__device__ __forceinline__ uint32_t cvt2(float f0, float f1) {
    uint32_t r;
    asm("cvt.rn.bf16x2.f32 %0, %1, %2;" : "=r"(r) : "f"(f1), "f"(f0));
    return r;
}

// 8 fp32 -> 8 bf16 hi (16B) + 8 bf16 lo (16B)
__device__ __forceinline__ void cvt_store8(const float4 a, const float4 b,
                                           char* hp_ptr, char* lp_ptr) {
    float f[8] = {a.x, a.y, a.z, a.w, b.x, b.y, b.z, b.w};
    uint32_t hp[4], lp[4];
#pragma unroll
    for (int p = 0; p < 4; ++p) {
        float f0 = f[2*p], f1 = f[2*p+1];
        uint32_t h = cvt2(f0, f1);
        hp[p] = h;
        float g0 = __uint_as_float(h << 16);
        float g1 = __uint_as_float(h & 0xFFFF0000u);
        lp[p] = cvt2(f0 - g0, f1 - g1);
    }
    *(uint4*)hp_ptr = make_uint4(hp[0], hp[1], hp[2], hp[3]);
    *(uint4*)lp_ptr = make_uint4(lp[0], lp[1], lp[2], lp[3]);
}

#define LDSM_X4(r0, r1, r2, r3, addr) \
    asm volatile("ldmatrix.sync.aligned.m8n8.x4.shared.b16 {%0,%1,%2,%3}, [%4];" \
                 : "=r"(r0), "=r"(r1), "=r"(r2), "=r"(r3) : "r"(addr))

#define MMA16816(d, a0, a1, a2, a3, b0, b1) \
    asm volatile("mma.sync.aligned.m16n8k16.row.col.f32.bf16.bf16.f32 " \
                 "{%0,%1,%2,%3}, {%4,%5,%6,%7}, {%8,%9}, {%0,%1,%2,%3};" \
                 : "+f"((d)[0]), "+f"((d)[1]), "+f"((d)[2]), "+f"((d)[3]) \
                 : "r"(a0), "r"(a1), "r"(a2), "r"(a3), "r"(b0), "r"(b1))

__global__ __launch_bounds__(THREADS, 1)
void edge_mlp_hmma(const float* __restrict__ zi, const float* __restrict__ zj,
                   const int* __restrict__ src, const int* __restrict__ dst,
                   const float* __restrict__ W1, const float* __restrict__ b1,
                   const float* __restrict__ W3, const float* __restrict__ b3,
                   float* __restrict__ out, int E, int ntiles)
{
    extern __shared__ char sm[];
    const uint32_t smu = smem_u32(sm);

    const int tid  = threadIdx.x;
    const int wid  = tid >> 5;
    const int lane = tid & 31;

    // ---- one-time: W1[k][n] -> B[n][k] hi/lo bf16 (resident) ----
    for (int it = tid; it < KDIM * HID; it += THREADS) {
        int k = it >> 7, n = it & 127;
        float x = W1[it];
        __nv_bfloat16 hb = __float2bfloat16(x);
        float l = x - __bfloat162float(hb);
        __nv_bfloat16 lb = __float2bfloat16(l);
        uint32_t off = (uint32_t)(n * BKS + k) * 2u;
        *(__nv_bfloat16*)(sm + OFF_BHI + off) = hb;
        *(__nv_bfloat16*)(sm + OFF_BLO + off) = lb;
    }
    if (tid < HID) {
        ((float*)(sm + OFF_B1))[tid] = b1[tid];
        ((float*)(sm + OFF_W3))[tid] = W3[tid];
    }
    __syncthreads();

    const float bb3 = __ldg(b3);
    const float* sb1 = (const float*)(sm + OFF_B1);
    const float* sw3 = (const float*)(sm + OFF_W3);
    float* spart = (float*)(sm + OFF_PART);

    // ---- warp tiling: 4x4 warps, each 32(M) x 32(N) ----
    const int warp_m = wid >> 2;
    const int warp_n = wid & 3;
    const int m0 = warp_m * 32;
    const int n0 = warp_n * 32;

    // ldmatrix per-lane base addresses (term 0 = hi; +A_TERM_BYTES = lo)
    const int rowA   = lane & 15;
    const int khalfA = lane >> 4;
    uint32_t abase[2];                   // [mt], hi-term, buf0
#pragma unroll
    for (int mt = 0; mt < 2; ++mt)
        abase[mt] = smu + OFF_A
                  + (uint32_t)((m0 + mt * 16 + rowA) * AKS + khalfA * 8) * 2u;

    const int rowB   = (lane & 7) + ((lane >= 16) ? 8 : 0);
    const int khalfB = (lane >> 3) & 1;
    uint32_t bbase[2];                   // [nt], hi-term
#pragma unroll
    for (int nt = 0; nt < 2; ++nt)
        bbase[nt] = smu + OFF_BHI
                  + (uint32_t)((n0 + nt * 16 + rowB) * BKS + khalfB * 8) * 2u;

    // gather assignment: edge slot e, 16-float slice qq of the 64-float chunk
    const int e  = tid >> 2;
    const int qq = tid & 3;
    const uint32_t a_sts = (uint32_t)(e * AKS + qq * 16) * 2u;

    // ---- prologue: first tile's indices + chunk0 prefetch ----
    int ge0 = blockIdx.x * TILE_M + e;
    int isrc = __ldg(&src[ge0 < E ? ge0 : (E - 1)]);
    int idst = __ldg(&dst[ge0 < E ? ge0 : (E - 1)]);
    const float* pre = zi + (size_t)isrc * DF + qq * 16;
    float4 r0 = *(const float4*)(pre + 0);
    float4 r1 = *(const float4*)(pre + 4);
    float4 r2 = *(const float4*)(pre + 8);
    float4 r3 = *(const float4*)(pre + 12);

    int nsrc = 0, ndst = 0;

    for (int tile = blockIdx.x; tile < ntiles; tile += GRID) {
        const int e0 = tile * TILE_M;
        const float* pi = zi + (size_t)isrc * DF + qq * 16;
        const float* pj = zj + (size_t)idst * DF + qq * 16;

        float acc[2][4][4];
#pragma unroll
        for (int mt = 0; mt < 2; ++mt)
#pragma unroll
            for (int nt8 = 0; nt8 < 4; ++nt8)
#pragma unroll
                for (int r = 0; r < 4; ++r) acc[mt][nt8][r] = 0.f;

#pragma unroll 1
        for (int c = 0; c < 4; ++c) {
            const uint32_t bufo = (uint32_t)(c & 1) * A_BUF_BYTES;
            // store chunk c into buffer (buf b last read at chunk c-2; that
            // read completed before the sync of chunk c-1)
            char* ah = sm + OFF_A + bufo;
            char* al = ah + A_TERM_BYTES;
            cvt_store8(r0, r1, ah + a_sts,      al + a_sts);
            cvt_store8(r2, r3, ah + a_sts + 16, al + a_sts + 16);

            // issue next LDGs (hidden under this chunk's mma)
            if (c == 0) {
                r0 = *(const float4*)(pi + 64); r1 = *(const float4*)(pi + 68);
                r2 = *(const float4*)(pi + 72); r3 = *(const float4*)(pi + 76);
            } else if (c == 1) {
                r0 = *(const float4*)(pj + 0);  r1 = *(const float4*)(pj + 4);
                r2 = *(const float4*)(pj + 8);  r3 = *(const float4*)(pj + 12);
            } else if (c == 2) {
                r0 = *(const float4*)(pj + 64); r1 = *(const float4*)(pj + 68);
                r2 = *(const float4*)(pj + 72); r3 = *(const float4*)(pj + 76);
                int nge = (tile + GRID < ntiles) ? (tile + GRID) * TILE_M + e : 0;
                nge = nge < E ? nge : (E - 1);
                nsrc = __ldg(&src[nge]);
                ndst = __ldg(&dst[nge]);
            } else {
                const float* np = zi + (size_t)nsrc * DF + qq * 16;
                r0 = *(const float4*)(np + 0);  r1 = *(const float4*)(np + 4);
                r2 = *(const float4*)(np + 8);  r3 = *(const float4*)(np + 12);
            }

            __syncthreads();   // single barrier per chunk

            const uint32_t bko = (uint32_t)c * 128u;
#pragma unroll
            for (int ks = 0; ks < 4; ++ks) {
                const uint32_t ao = bufo + (uint32_t)ks * 32u;
                const uint32_t bo = bko + (uint32_t)ks * 32u;
                uint32_t Ah[2][4], Al[2][4], Bh[2][4], Bl[2][4];
#pragma unroll
                for (int mt = 0; mt < 2; ++mt) {
                    LDSM_X4(Ah[mt][0], Ah[mt][1], Ah[mt][2], Ah[mt][3],
                            abase[mt] + ao);
                    LDSM_X4(Al[mt][0], Al[mt][1], Al[mt][2], Al[mt][3],
                            abase[mt] + ao + A_TERM_BYTES);
                }
#pragma unroll
                for (int nt = 0; nt < 2; ++nt) {
                    LDSM_X4(Bh[nt][0], Bh[nt][1], Bh[nt][2], Bh[nt][3],
                            bbase[nt] + bo);
                    LDSM_X4(Bl[nt][0], Bl[nt][1], Bl[nt][2], Bl[nt][3],
                            bbase[nt] + bo + 67584u);
                }
                // term-ordered: same-accumulator MMAs are 8 issues apart
#pragma unroll
                for (int mt = 0; mt < 2; ++mt)
#pragma unroll
                    for (int nt8 = 0; nt8 < 4; ++nt8) {
                        const int nt = nt8 >> 1, hf = (nt8 & 1) * 2;
                        MMA16816(acc[mt][nt8],
                                 Ah[mt][0], Ah[mt][1], Ah[mt][2], Ah[mt][3],
                                 Bh[nt][hf], Bh[nt][hf + 1]);
                    }
#pragma unroll
                for (int mt = 0; mt < 2; ++mt)
#pragma unroll
                    for (int nt8 = 0; nt8 < 4; ++nt8) {
                        const int nt = nt8 >> 1, hf = (nt8 & 1) * 2;
                        MMA16816(acc[mt][nt8],
                                 Al[mt][0], Al[mt][1], Al[mt][2], Al[mt][3],
                                 Bh[nt][hf], Bh[nt][hf + 1]);
                    }
#pragma unroll
                for (int mt = 0; mt < 2; ++mt)
#pragma unroll
                    for (int nt8 = 0; nt8 < 4; ++nt8) {
                        const int nt = nt8 >> 1, hf = (nt8 & 1) * 2;
                        MMA16816(acc[mt][nt8],
                                 Ah[mt][0], Ah[mt][1], Ah[mt][2], Ah[mt][3],
                                 Bl[nt][hf], Bl[nt][hf + 1]);
                    }
            }
        }

        // ---- epilogue: bias+relu+W3 from register fragments ----
        const int g  = lane >> 2;
        const int c0 = (lane & 3) * 2;
        float p[4];
#pragma unroll
        for (int mt = 0; mt < 2; ++mt) {
            float s0 = 0.f, s1 = 0.f;
#pragma unroll
            for (int nt8 = 0; nt8 < 4; ++nt8) {
                const int n = n0 + nt8 * 8 + c0;
                const float w0 = sw3[n], w1 = sw3[n + 1];
                const float bb0 = sb1[n], bb1 = sb1[n + 1];
                s0 = fmaf(fmaxf(acc[mt][nt8][0] + bb0, 0.f), w0, s0);
                s0 = fmaf(fmaxf(acc[mt][nt8][1] + bb1, 0.f), w1, s0);
                s1 = fmaf(fmaxf(acc[mt][nt8][2] + bb0, 0.f), w0, s1);
                s1 = fmaf(fmaxf(acc[mt][nt8][3] + bb1, 0.f), w1, s1);
            }
            p[mt * 2 + 0] = s0;
            p[mt * 2 + 1] = s1;
        }
#pragma unroll
        for (int i = 0; i < 4; ++i) {
            p[i] += __shfl_xor_sync(0xffffffffu, p[i], 1);
            p[i] += __shfl_xor_sync(0xffffffffu, p[i], 2);
        }
        if ((lane & 3) == 0) {
#pragma unroll
            for (int i = 0; i < 4; ++i) {
                const int m = m0 + (i >> 1) * 16 + (i & 1) * 8 + g;
                spart[m * 4 + warp_n] = p[i];
            }
        }
        isrc = nsrc;          // roll prefetched indices into place
        idst = ndst;
        __syncthreads();
        if (tid < TILE_M) {
            const int ge = e0 + tid;
            if (ge < E) {
                float tot = spart[tid * 4 + 0] + spart[tid * 4 + 1]
                          + spart[tid * 4 + 2] + spart[tid * 4 + 3] + bb3;
                out[ge] = 1.0f / (1.0f + __expf(-tot));
            }
        }
        __syncthreads();
    }
}

extern "C" void kernel_launch(void* const* d_in, const int* in_sizes, int n_in,
                              void* d_out, int out_size) {
    const float* zi = (const float*)d_in[0];
    const float* zj = (const float*)d_in[1];
    const int*   src = (const int*)d_in[2];
    const int*   dst = (const int*)d_in[3];
    const float* W1 = (const float*)d_in[4];
    const float* b1 = (const float*)d_in[5];
    const float* W3 = (const float*)d_in[6];
    const float* b3 = (const float*)d_in[7];
    float* out = (float*)d_out;

    const int E = in_sizes[2];
    const int ntiles = (E + TILE_M - 1) / TILE_M;

    cudaFuncSetAttribute(edge_mlp_hmma,
                         cudaFuncAttributeMaxDynamicSharedMemorySize, SMEM_REQ);
    edge_mlp_hmma<<<GRID, THREADS, SMEM_REQ>>>(zi, zj, src, dst, W1, b1, W3, b3,
                                               out, E, ntiles);
}